// round 8
// baseline (speedup 1.0000x reference)
#include <cuda_runtime.h>
#include <cstdint>

// Barrier-free DCN CrossLayer: each WARP independently owns 4 rows.
// Dot phase: loop over 8 column-stripes; per stripe load w0/w1/w2 from
// shared ONCE and apply to 4 rows (weight-LDS amortized 4x).
// Reduce: one 12-partial butterfly per 4 rows, per warp (no cross-warp).
// Store phase: re-read x (L2 hit), out = alpha*x + betasum (bs from shared).
// No __syncthreads in steady state; block barrier only in the prologue.

#define F_DIM 1024
#define NVEC  256
#define THREADS 256
#define NW 8            // warps per block
#define RW 4            // rows per warp

__device__ __forceinline__ float dot4(float4 a, float4 b, float acc) {
    return fmaf(a.x, b.x, fmaf(a.y, b.y, fmaf(a.z, b.z, fmaf(a.w, b.w, acc))));
}

__global__ __launch_bounds__(THREADS, 4)
void cross_warp4_kernel(const float* __restrict__ x,
                        const float* __restrict__ kernels,
                        const float* __restrict__ bias,
                        float* __restrict__ out,
                        int B)
{
    __shared__ float4 sw0[NVEC];
    __shared__ float4 sw1[NVEC];
    __shared__ float4 sw2[NVEC];
    __shared__ float4 sbs[NVEC];
    __shared__ float  red[2][NW];
    __shared__ float  sc01, sc012;

    const int t   = threadIdx.x;     // 0..255 == float4 column
    const int wid = t >> 5;
    const int lid = t & 31;

    // ---- Prologue: stage weights/biases, compute cross constants ----
    {
        const float4* __restrict__ k4 = reinterpret_cast<const float4*>(kernels);
        const float4* __restrict__ b4 = reinterpret_cast<const float4*>(bias);
        const float4 w0 = __ldg(&k4[t]);
        const float4 w1 = __ldg(&k4[NVEC + t]);
        const float4 w2 = __ldg(&k4[2 * NVEC + t]);
        const float4 b0 = __ldg(&b4[t]);
        const float4 b1 = __ldg(&b4[NVEC + t]);
        const float4 b2 = __ldg(&b4[2 * NVEC + t]);
        sw0[t] = w0; sw1[t] = w1; sw2[t] = w2;
        float4 bsv;
        bsv.x = b0.x + b1.x + b2.x;
        bsv.y = b0.y + b1.y + b2.y;
        bsv.z = b0.z + b1.z + b2.z;
        bsv.w = b0.w + b1.w + b2.w;
        sbs[t] = bsv;

        float pc01 = dot4(b0, w1, 0.f);
        float4 b01;
        b01.x = b0.x + b1.x; b01.y = b0.y + b1.y;
        b01.z = b0.z + b1.z; b01.w = b0.w + b1.w;
        float pc012 = dot4(b01, w2, 0.f);
        #pragma unroll
        for (int off = 16; off; off >>= 1) {
            pc01  += __shfl_xor_sync(0xFFFFFFFFu, pc01,  off);
            pc012 += __shfl_xor_sync(0xFFFFFFFFu, pc012, off);
        }
        if (lid == 0) { red[0][wid] = pc01; red[1][wid] = pc012; }
    }
    __syncthreads();
    const float c01  = red[0][0] + red[0][1] + red[0][2] + red[0][3]
                     + red[0][4] + red[0][5] + red[0][6] + red[0][7];
    const float c012 = red[1][0] + red[1][1] + red[1][2] + red[1][3]
                     + red[1][4] + red[1][5] + red[1][6] + red[1][7];

    // ---- Steady state: warp owns rows [4*gw, 4*gw+4), fully independent ----
    const int gw   = blockIdx.x * NW + wid;
    const int row0 = gw * RW;
    if (row0 >= B) return;

    const float4* __restrict__ xb =
        reinterpret_cast<const float4*>(x) + (size_t)row0 * NVEC;
    float4* __restrict__ ob =
        reinterpret_cast<float4*>(out) + (size_t)row0 * NVEC;

    // Dot phase: 8 stripes, weights loaded once per stripe, 4 rows each.
    float p[12];
    #pragma unroll
    for (int j = 0; j < 12; j++) p[j] = 0.f;

    #pragma unroll
    for (int k = 0; k < 8; k++) {
        const int c = k * 32 + lid;
        const float4 x0 = xb[c];
        const float4 x1 = xb[NVEC + c];
        const float4 x2 = xb[2 * NVEC + c];
        const float4 x3 = xb[3 * NVEC + c];
        const float4 a0 = sw0[c];
        const float4 a1 = sw1[c];
        const float4 a2 = sw2[c];
        p[0] = dot4(x0, a0, p[0]);  p[4]  = dot4(x0, a1, p[4]);  p[8]  = dot4(x0, a2, p[8]);
        p[1] = dot4(x1, a0, p[1]);  p[5]  = dot4(x1, a1, p[5]);  p[9]  = dot4(x1, a2, p[9]);
        p[2] = dot4(x2, a0, p[2]);  p[6]  = dot4(x2, a1, p[6]);  p[10] = dot4(x2, a2, p[10]);
        p[3] = dot4(x3, a0, p[3]);  p[7]  = dot4(x3, a1, p[7]);  p[11] = dot4(x3, a2, p[11]);
    }

    // One butterfly per 4 rows (12 independent chains).
    #pragma unroll
    for (int off = 16; off; off >>= 1) {
        #pragma unroll
        for (int j = 0; j < 12; j++)
            p[j] += __shfl_xor_sync(0xFFFFFFFFu, p[j], off);
    }

    // Alphas for the 4 rows (computed redundantly in every lane).
    float alpha[RW];
    #pragma unroll
    for (int r = 0; r < RW; r++) {
        const float t1 = 1.f + p[r];
        const float s1 = fmaf(t1, p[4 + r], c01);
        const float t2 = t1 + s1;
        const float s2 = fmaf(t2, p[8 + r], c012);
        alpha[r] = t2 + s2;
    }

    // Store phase: re-read x (L2-hot), bs from shared, streaming stores.
    #pragma unroll
    for (int k = 0; k < 8; k++) {
        const int c = k * 32 + lid;
        const float4 bsv = sbs[c];
        const float4 x0 = xb[c];
        const float4 x1 = xb[NVEC + c];
        const float4 x2 = xb[2 * NVEC + c];
        const float4 x3 = xb[3 * NVEC + c];
        float4 o0, o1, o2, o3;
        o0.x = fmaf(alpha[0], x0.x, bsv.x); o0.y = fmaf(alpha[0], x0.y, bsv.y);
        o0.z = fmaf(alpha[0], x0.z, bsv.z); o0.w = fmaf(alpha[0], x0.w, bsv.w);
        o1.x = fmaf(alpha[1], x1.x, bsv.x); o1.y = fmaf(alpha[1], x1.y, bsv.y);
        o1.z = fmaf(alpha[1], x1.z, bsv.z); o1.w = fmaf(alpha[1], x1.w, bsv.w);
        o2.x = fmaf(alpha[2], x2.x, bsv.x); o2.y = fmaf(alpha[2], x2.y, bsv.y);
        o2.z = fmaf(alpha[2], x2.z, bsv.z); o2.w = fmaf(alpha[2], x2.w, bsv.w);
        o3.x = fmaf(alpha[3], x3.x, bsv.x); o3.y = fmaf(alpha[3], x3.y, bsv.y);
        o3.z = fmaf(alpha[3], x3.z, bsv.z); o3.w = fmaf(alpha[3], x3.w, bsv.w);
        __stcs(&ob[c], o0);
        __stcs(&ob[NVEC + c], o1);
        __stcs(&ob[2 * NVEC + c], o2);
        __stcs(&ob[3 * NVEC + c], o3);
    }
}

extern "C" void kernel_launch(void* const* d_in, const int* in_sizes, int n_in,
                              void* d_out, int out_size)
{
    const float* x       = (const float*)d_in[0];
    const float* kernels = (const float*)d_in[1];
    const float* bias    = (const float*)d_in[2];
    float* out           = (float*)d_out;

    const int B = in_sizes[0] / F_DIM;            // 16384
    const int rows_per_block = NW * RW;           // 32
    const int grid = (B + rows_per_block - 1) / rows_per_block;   // 512
    cross_warp4_kernel<<<grid, THREADS>>>(x, kernels, bias, out, B);
}

// round 10
// speedup vs baseline: 1.7945x; 1.7945x over previous
#include <cuda_runtime.h>
#include <cstdint>

// Persistent col-major DCN CrossLayer.
// Thread t owns float4 column t; w0/w1/w2/betasum in registers.
// Grid = 4 CTAs/SM exactly, grid-strided over 4-row tiles.
// Per tile: 4x LDG.128 -> 12 dots -> butterfly -> ONE syncthreads
//           -> all-warp redundant combine -> 4x STG.128.
// red[] double-buffered so one barrier per tile is WAR-safe.
// NOTE: the barrier is safe — `tile < ntiles` is uniform across the block
// (depends only on blockIdx), so all 256 threads iterate in lockstep.

#define F_DIM 1024
#define NVEC  256
#define THREADS 256
#define NWARPS 8
#define TILE_R 4
#define CTAS_PER_SM 4
#define NSM 148

__device__ __forceinline__ float dot4(float4 a, float4 b, float acc) {
    return fmaf(a.x, b.x, fmaf(a.y, b.y, fmaf(a.z, b.z, fmaf(a.w, b.w, acc))));
}

__global__ __launch_bounds__(THREADS, CTAS_PER_SM)
void cross_persist_kernel(const float* __restrict__ x,
                          const float* __restrict__ kernels,
                          const float* __restrict__ bias,
                          float* __restrict__ out,
                          int ntiles)
{
    __shared__ float red[2][12][NWARPS];

    const int t   = threadIdx.x;        // float4 column 0..255
    const int wid = t >> 5;
    const int lid = t & 31;

    // ---- Prologue: per-column weights into registers ----
    const float4* __restrict__ k4 = reinterpret_cast<const float4*>(kernels);
    const float4* __restrict__ b4 = reinterpret_cast<const float4*>(bias);
    const float4 w0 = __ldg(&k4[t]);
    const float4 w1 = __ldg(&k4[NVEC + t]);
    const float4 w2 = __ldg(&k4[2 * NVEC + t]);
    const float4 b0 = __ldg(&b4[t]);
    const float4 b1 = __ldg(&b4[NVEC + t]);
    const float4 b2 = __ldg(&b4[2 * NVEC + t]);
    float4 bs;
    bs.x = b0.x + b1.x + b2.x;
    bs.y = b0.y + b1.y + b2.y;
    bs.z = b0.z + b1.z + b2.z;
    bs.w = b0.w + b1.w + b2.w;

    // cross constants: c01 = b0.w1, c012 = (b0+b1).w2
    float c01, c012;
    {
        float pc01 = dot4(b0, w1, 0.f);
        float4 b01;
        b01.x = b0.x + b1.x; b01.y = b0.y + b1.y;
        b01.z = b0.z + b1.z; b01.w = b0.w + b1.w;
        float pc012 = dot4(b01, w2, 0.f);
        #pragma unroll
        for (int off = 16; off; off >>= 1) {
            pc01  += __shfl_xor_sync(0xFFFFFFFFu, pc01,  off);
            pc012 += __shfl_xor_sync(0xFFFFFFFFu, pc012, off);
        }
        if (lid == 0) { red[0][0][wid] = pc01; red[0][1][wid] = pc012; }
        __syncthreads();
        float a = 0.f, b = 0.f;
        #pragma unroll
        for (int i = 0; i < NWARPS; i++) { a += red[0][0][i]; b += red[0][1][i]; }
        c01 = a; c012 = b;
        __syncthreads();     // protect red[0] before the main loop reuses it
    }

    const float4* __restrict__ x4 = reinterpret_cast<const float4*>(x);
    float4* __restrict__ o4       = reinterpret_cast<float4*>(out);

    int it = 0;
    #pragma unroll 1
    for (int tile = blockIdx.x; tile < ntiles; tile += gridDim.x, ++it) {
        const size_t base = (size_t)tile * TILE_R * NVEC + t;

        // ---- Load 4 rows' float4 (batched) + 12 dots ----
        float4 xs[TILE_R];
        #pragma unroll
        for (int r = 0; r < TILE_R; r++)
            xs[r] = __ldcs(&x4[base + (size_t)r * NVEC]);

        float p[12];
        #pragma unroll
        for (int r = 0; r < TILE_R; r++) {
            p[r]     = dot4(xs[r], w0, 0.f);
            p[4 + r] = dot4(xs[r], w1, 0.f);
            p[8 + r] = dot4(xs[r], w2, 0.f);
        }

        // ---- Butterfly over 12 independent partials ----
        #pragma unroll
        for (int off = 16; off; off >>= 1) {
            #pragma unroll
            for (int j = 0; j < 12; j++)
                p[j] += __shfl_xor_sync(0xFFFFFFFFu, p[j], off);
        }

        const int buf = it & 1;
        if (lid == 0) {
            #pragma unroll
            for (int j = 0; j < 12; j++) red[buf][j][wid] = p[j];
        }
        __syncthreads();                 // the only barrier per tile

        // ---- All-warp redundant combine ----
        float val = 0.f;
        if (lid < 12) {
            #pragma unroll
            for (int w = 0; w < NWARPS; w++) val += red[buf][lid][w];
        }

        // ---- Alphas + stores (x still in registers) ----
        #pragma unroll
        for (int r = 0; r < TILE_R; r++) {
            const float d0 = __shfl_sync(0xFFFFFFFFu, val, r);
            const float d1 = __shfl_sync(0xFFFFFFFFu, val, 4 + r);
            const float d2 = __shfl_sync(0xFFFFFFFFu, val, 8 + r);
            const float t1 = 1.f + d0;
            const float s1 = fmaf(t1, d1, c01);
            const float t2 = t1 + s1;
            const float s2 = fmaf(t2, d2, c012);
            const float a  = t2 + s2;
            float4 o;
            o.x = fmaf(a, xs[r].x, bs.x);
            o.y = fmaf(a, xs[r].y, bs.y);
            o.z = fmaf(a, xs[r].z, bs.z);
            o.w = fmaf(a, xs[r].w, bs.w);
            __stcs(&o4[base + (size_t)r * NVEC], o);
        }
    }
}

extern "C" void kernel_launch(void* const* d_in, const int* in_sizes, int n_in,
                              void* d_out, int out_size)
{
    const float* x       = (const float*)d_in[0];
    const float* kernels = (const float*)d_in[1];
    const float* bias    = (const float*)d_in[2];
    float* out           = (float*)d_out;

    const int B = in_sizes[0] / F_DIM;              // 16384
    const int ntiles = (B + TILE_R - 1) / TILE_R;   // 4096
    int grid = NSM * CTAS_PER_SM;                   // 592
    if (grid > ntiles) grid = ntiles;

    cross_persist_kernel<<<grid, THREADS>>>(x, kernels, bias, out, ntiles);
}

// round 13
// speedup vs baseline: 1.8024x; 1.0044x over previous
#include <cuda_runtime.h>
#include <cstdint>

// Persistent col-major DCN CrossLayer with THREAD-PRIVATE cp.async pipeline.
// Thread t owns float4 column t. Each thread cp.async-copies ITS OWN slice of
// the next 4-row tile into smem (slot ring of 2); since the same thread later
// reads exactly those bytes, no barrier is needed for staging — wait_group 1
// gives per-thread readiness, and slot WAR is program-order-safe.
// Per tile: issue next-tile cp.async -> wait_group -> LDS + 12 dots ->
// butterfly -> ONE syncthreads (combine) -> re-LDS + STG.

#define F_DIM 1024
#define NVEC  256
#define THREADS 256
#define NWARPS 8
#define TILE_R 4
#define CTAS_PER_SM 5
#define NSM 148

__device__ __forceinline__ float dot4(float4 a, float4 b, float acc) {
    return fmaf(a.x, b.x, fmaf(a.y, b.y, fmaf(a.z, b.z, fmaf(a.w, b.w, acc))));
}
__device__ __forceinline__ uint32_t s2u(const void* p) {
    return (uint32_t)__cvta_generic_to_shared(p);
}
__device__ __forceinline__ void cp16(uint32_t dst, const void* src) {
    asm volatile("cp.async.cg.shared.global [%0], [%1], 16;"
                 :: "r"(dst), "l"(src) : "memory");
}
__device__ __forceinline__ void cp_commit() {
    asm volatile("cp.async.commit_group;" ::: "memory");
}
__device__ __forceinline__ void cp_wait1() {
    asm volatile("cp.async.wait_group 1;" ::: "memory");
}
__device__ __forceinline__ void cp_wait0() {
    asm volatile("cp.async.wait_group 0;" ::: "memory");
}

__global__ __launch_bounds__(THREADS, CTAS_PER_SM)
void cross_cpa_kernel(const float* __restrict__ x,
                      const float* __restrict__ kernels,
                      const float* __restrict__ bias,
                      float* __restrict__ out,
                      int ntiles)
{
    __shared__ float4 slot[2][TILE_R * NVEC];     // 2 x 16KB
    __shared__ float  red[2][12][NWARPS];

    const int t   = threadIdx.x;        // float4 column 0..255
    const int wid = t >> 5;
    const int lid = t & 31;

    // ---- Prologue: per-column weights into registers ----
    const float4* __restrict__ k4 = reinterpret_cast<const float4*>(kernels);
    const float4* __restrict__ b4 = reinterpret_cast<const float4*>(bias);
    const float4 w0 = __ldg(&k4[t]);
    const float4 w1 = __ldg(&k4[NVEC + t]);
    const float4 w2 = __ldg(&k4[2 * NVEC + t]);
    const float4 b0 = __ldg(&b4[t]);
    const float4 b1 = __ldg(&b4[NVEC + t]);
    const float4 b2 = __ldg(&b4[2 * NVEC + t]);
    float4 bs;
    bs.x = b0.x + b1.x + b2.x;
    bs.y = b0.y + b1.y + b2.y;
    bs.z = b0.z + b1.z + b2.z;
    bs.w = b0.w + b1.w + b2.w;

    // cross constants: c01 = b0.w1, c012 = (b0+b1).w2
    float c01, c012;
    {
        float pc01 = dot4(b0, w1, 0.f);
        float4 b01;
        b01.x = b0.x + b1.x; b01.y = b0.y + b1.y;
        b01.z = b0.z + b1.z; b01.w = b0.w + b1.w;
        float pc012 = dot4(b01, w2, 0.f);
        #pragma unroll
        for (int off = 16; off; off >>= 1) {
            pc01  += __shfl_xor_sync(0xFFFFFFFFu, pc01,  off);
            pc012 += __shfl_xor_sync(0xFFFFFFFFu, pc012, off);
        }
        if (lid == 0) { red[0][0][wid] = pc01; red[0][1][wid] = pc012; }
        __syncthreads();
        float a = 0.f, b = 0.f;
        #pragma unroll
        for (int i = 0; i < NWARPS; i++) { a += red[0][0][i]; b += red[0][1][i]; }
        c01 = a; c012 = b;
        __syncthreads();     // protect red[0] before main loop reuses it
    }

    const float* __restrict__ xf = x;
    float4* __restrict__ o4      = reinterpret_cast<float4*>(out);

    const int tile0 = blockIdx.x;
    const int gstep = gridDim.x;

    // Per-thread smem addresses for its 4 float4 slots (one per row).
    uint32_t sdst[2];
    sdst[0] = s2u(&slot[0][t]);
    sdst[1] = s2u(&slot[1][t]);

    // Prologue: stage tile0 (group becomes the "oldest" group).
    if (tile0 < ntiles) {
        const float* src = xf + (size_t)tile0 * TILE_R * F_DIM + t * 4;
        #pragma unroll
        for (int r = 0; r < TILE_R; r++)
            cp16(sdst[0] + r * (NVEC * 16), src + r * F_DIM);
    }
    cp_commit();

    int it = 0;
    #pragma unroll 1
    for (int tile = tile0; tile < ntiles; tile += gstep, ++it) {
        const int cur = it & 1;
        const int nxt = cur ^ 1;

        // ---- Issue next tile's copies (thread-private slice) ----
        {
            int ntile = tile + gstep;
            if (ntile >= ntiles) ntile = tile;    // clamp: harmless re-copy
            const float* src = xf + (size_t)ntile * TILE_R * F_DIM + t * 4;
            #pragma unroll
            for (int r = 0; r < TILE_R; r++)
                cp16(sdst[nxt] + r * (NVEC * 16), src + r * F_DIM);
        }
        cp_commit();
        cp_wait1();                                // current tile resident

        // ---- Dot phase from smem ----
        float p[12];
        {
            const float4 x0 = slot[cur][t];
            const float4 x1 = slot[cur][NVEC + t];
            const float4 x2 = slot[cur][2 * NVEC + t];
            const float4 x3 = slot[cur][3 * NVEC + t];
            p[0] = dot4(x0, w0, 0.f); p[4] = dot4(x0, w1, 0.f); p[8]  = dot4(x0, w2, 0.f);
            p[1] = dot4(x1, w0, 0.f); p[5] = dot4(x1, w1, 0.f); p[9]  = dot4(x1, w2, 0.f);
            p[2] = dot4(x2, w0, 0.f); p[6] = dot4(x2, w1, 0.f); p[10] = dot4(x2, w2, 0.f);
            p[3] = dot4(x3, w0, 0.f); p[7] = dot4(x3, w1, 0.f); p[11] = dot4(x3, w2, 0.f);
        }

        // ---- Butterfly over 12 independent partials ----
        #pragma unroll
        for (int off = 16; off; off >>= 1) {
            #pragma unroll
            for (int j = 0; j < 12; j++)
                p[j] += __shfl_xor_sync(0xFFFFFFFFu, p[j], off);
        }

        const int buf = it & 1;
        if (lid == 0) {
            #pragma unroll
            for (int j = 0; j < 12; j++) red[buf][j][wid] = p[j];
        }
        __syncthreads();                 // the only block barrier per tile

        // ---- All-warp redundant combine ----
        float val = 0.f;
        if (lid < 12) {
            #pragma unroll
            for (int w = 0; w < NWARPS; w++) val += red[buf][lid][w];
        }

        // ---- Store phase: re-read x from smem (still valid: only this
        //      thread overwrites its slot, and only at the NEXT iteration) ----
        const size_t base = (size_t)tile * TILE_R * NVEC + t;
        #pragma unroll
        for (int r = 0; r < TILE_R; r++) {
            const float d0 = __shfl_sync(0xFFFFFFFFu, val, r);
            const float d1 = __shfl_sync(0xFFFFFFFFu, val, 4 + r);
            const float d2 = __shfl_sync(0xFFFFFFFFu, val, 8 + r);
            const float t1 = 1.f + d0;
            const float s1 = fmaf(t1, d1, c01);
            const float t2 = t1 + s1;
            const float s2 = fmaf(t2, d2, c012);
            const float a  = t2 + s2;
            const float4 xv = slot[cur][r * NVEC + t];
            float4 o;
            o.x = fmaf(a, xv.x, bs.x);
            o.y = fmaf(a, xv.y, bs.y);
            o.z = fmaf(a, xv.z, bs.z);
            o.w = fmaf(a, xv.w, bs.w);
            __stcs(&o4[base + (size_t)r * NVEC], o);
        }
    }
    cp_wait0();   // drain before exit
}

extern "C" void kernel_launch(void* const* d_in, const int* in_sizes, int n_in,
                              void* d_out, int out_size)
{
    const float* x       = (const float*)d_in[0];
    const float* kernels = (const float*)d_in[1];
    const float* bias    = (const float*)d_in[2];
    float* out           = (float*)d_out;

    const int B = in_sizes[0] / F_DIM;              // 16384
    const int ntiles = (B + TILE_R - 1) / TILE_R;   // 4096
    int grid = NSM * CTAS_PER_SM;                   // 740
    if (grid > ntiles) grid = ntiles;

    cross_cpa_kernel<<<grid, THREADS>>>(x, kernels, bias, out, ntiles);
}

// round 14
// speedup vs baseline: 2.0741x; 1.1507x over previous
#include <cuda_runtime.h>
#include <cstdint>

// Persistent col-major DCN CrossLayer (R10 base) with multi-value FOLD
// reduction: 12 partials reduced in 13 SHFL + 13 FADD instead of a full
// 60-SHFL butterfly. Final sums land on 12 canonical lanes which write
// red[] directly. One __syncthreads per tile; red double-buffered.

#define F_DIM 1024
#define NVEC  256
#define THREADS 256
#define NWARPS 8
#define TILE_R 4
#define CTAS_PER_SM 4
#define NSM 148

__device__ __forceinline__ float dot4(float4 a, float4 b, float acc) {
    return fmaf(a.x, b.x, fmaf(a.y, b.y, fmaf(a.z, b.z, fmaf(a.w, b.w, acc))));
}

__global__ __launch_bounds__(THREADS, CTAS_PER_SM)
void cross_fold_kernel(const float* __restrict__ x,
                       const float* __restrict__ kernels,
                       const float* __restrict__ bias,
                       float* __restrict__ out,
                       int ntiles)
{
    __shared__ float red[2][12][NWARPS];

    const int t   = threadIdx.x;        // float4 column 0..255
    const int wid = t >> 5;
    const int lid = t & 31;

    // ---- Prologue: per-column weights into registers ----
    const float4* __restrict__ k4 = reinterpret_cast<const float4*>(kernels);
    const float4* __restrict__ b4 = reinterpret_cast<const float4*>(bias);
    const float4 w0 = __ldg(&k4[t]);
    const float4 w1 = __ldg(&k4[NVEC + t]);
    const float4 w2 = __ldg(&k4[2 * NVEC + t]);
    const float4 b0 = __ldg(&b4[t]);
    const float4 b1 = __ldg(&b4[NVEC + t]);
    const float4 b2 = __ldg(&b4[2 * NVEC + t]);
    float4 bs;
    bs.x = b0.x + b1.x + b2.x;
    bs.y = b0.y + b1.y + b2.y;
    bs.z = b0.z + b1.z + b2.z;
    bs.w = b0.w + b1.w + b2.w;

    // cross constants: c01 = b0.w1, c012 = (b0+b1).w2
    float c01, c012;
    {
        float pc01 = dot4(b0, w1, 0.f);
        float4 b01;
        b01.x = b0.x + b1.x; b01.y = b0.y + b1.y;
        b01.z = b0.z + b1.z; b01.w = b0.w + b1.w;
        float pc012 = dot4(b01, w2, 0.f);
        #pragma unroll
        for (int off = 16; off; off >>= 1) {
            pc01  += __shfl_xor_sync(0xFFFFFFFFu, pc01,  off);
            pc012 += __shfl_xor_sync(0xFFFFFFFFu, pc012, off);
        }
        if (lid == 0) { red[0][0][wid] = pc01; red[0][1][wid] = pc012; }
        __syncthreads();
        float a = 0.f, b = 0.f;
        #pragma unroll
        for (int i = 0; i < NWARPS; i++) { a += red[0][0][i]; b += red[0][1][i]; }
        c01 = a; c012 = b;
        __syncthreads();     // protect red[0] before the main loop reuses it
    }

    const float4* __restrict__ x4 = reinterpret_cast<const float4*>(x);
    float4* __restrict__ o4       = reinterpret_cast<float4*>(out);

    // Fold-reduce lane bookkeeping (constant per thread).
    const int b4i = (lid >> 4) & 1;
    const int b3i = (lid >> 3) & 1;
    const int b2i = (lid >> 2) & 1;
    const int b1i = (lid >> 1) & 1;
    const int b0i = lid & 1;
    const int myidx  = 6 * b4i + 3 * b3i + (b1i ? 2 : b2i);
    const bool writer = (b0i == 0) && (b1i ? (b2i == 0) : true);

    int it = 0;
    #pragma unroll 1
    for (int tile = blockIdx.x; tile < ntiles; tile += gridDim.x, ++it) {
        const size_t base = (size_t)tile * TILE_R * NVEC + t;

        // ---- Load 4 rows' float4 (batched) + 12 dots ----
        float4 xs[TILE_R];
        #pragma unroll
        for (int r = 0; r < TILE_R; r++)
            xs[r] = __ldcs(&x4[base + (size_t)r * NVEC]);

        float p[12];
        #pragma unroll
        for (int r = 0; r < TILE_R; r++) {
            p[r]     = dot4(xs[r], w0, 0.f);
            p[4 + r] = dot4(xs[r], w1, 0.f);
            p[8 + r] = dot4(xs[r], w2, 0.f);
        }

        // ---- Fold reduction: 12 values -> 1 per lane (13 SHFL total) ----
        // Step 1 (xor 16): 12 -> 6
        float f6[6];
        {
            const bool hi = b4i;
            #pragma unroll
            for (int j = 0; j < 6; j++) {
                const float send = hi ? p[j] : p[j + 6];
                const float recv = __shfl_xor_sync(0xFFFFFFFFu, send, 16);
                f6[j] = (hi ? p[j + 6] : p[j]) + recv;
            }
        }
        // Step 2 (xor 8): 6 -> 3
        float f3[3];
        {
            const bool hi = b3i;
            #pragma unroll
            for (int j = 0; j < 3; j++) {
                const float send = hi ? f6[j] : f6[j + 3];
                const float recv = __shfl_xor_sync(0xFFFFFFFFu, send, 8);
                f3[j] = (hi ? f6[j + 3] : f6[j]) + recv;
            }
        }
        // Step 3 (xor 4): fold f3[0]/f3[1]; plain butterfly for f3[2]
        float z01, z2;
        {
            const bool hi = b2i;
            const float send = hi ? f3[0] : f3[1];
            const float recv = __shfl_xor_sync(0xFFFFFFFFu, send, 4);
            z01 = (hi ? f3[1] : f3[0]) + recv;
            z2  = f3[2] + __shfl_xor_sync(0xFFFFFFFFu, f3[2], 4);
        }
        // Step 4 (xor 2): fold z01/z2
        float zz;
        {
            const bool hi = b1i;
            const float send = hi ? z01 : z2;
            const float recv = __shfl_xor_sync(0xFFFFFFFFu, send, 2);
            zz = (hi ? z2 : z01) + recv;
        }
        // Step 5 (xor 1): final pair sum
        zz += __shfl_xor_sync(0xFFFFFFFFu, zz, 1);
        // lane now holds full sum of p[myidx]; canonical writers publish.

        const int buf = it & 1;
        if (writer) red[buf][myidx][wid] = zz;
        __syncthreads();                 // the only barrier per tile

        // ---- All-warp redundant combine ----
        float val = 0.f;
        if (lid < 12) {
            #pragma unroll
            for (int w = 0; w < NWARPS; w++) val += red[buf][lid][w];
        }

        // ---- Alphas + stores (x still in registers) ----
        #pragma unroll
        for (int r = 0; r < TILE_R; r++) {
            const float d0 = __shfl_sync(0xFFFFFFFFu, val, r);
            const float d1 = __shfl_sync(0xFFFFFFFFu, val, 4 + r);
            const float d2 = __shfl_sync(0xFFFFFFFFu, val, 8 + r);
            const float t1 = 1.f + d0;
            const float s1 = fmaf(t1, d1, c01);
            const float t2 = t1 + s1;
            const float s2 = fmaf(t2, d2, c012);
            const float a  = t2 + s2;
            float4 o;
            o.x = fmaf(a, xs[r].x, bs.x);
            o.y = fmaf(a, xs[r].y, bs.y);
            o.z = fmaf(a, xs[r].z, bs.z);
            o.w = fmaf(a, xs[r].w, bs.w);
            __stcs(&o4[base + (size_t)r * NVEC], o);
        }
    }
}

extern "C" void kernel_launch(void* const* d_in, const int* in_sizes, int n_in,
                              void* d_out, int out_size)
{
    const float* x       = (const float*)d_in[0];
    const float* kernels = (const float*)d_in[1];
    const float* bias    = (const float*)d_in[2];
    float* out           = (float*)d_out;

    const int B = in_sizes[0] / F_DIM;              // 16384
    const int ntiles = (B + TILE_R - 1) / TILE_R;   // 4096
    int grid = NSM * CTAS_PER_SM;                   // 592
    if (grid > ntiles) grid = ntiles;

    cross_fold_kernel<<<grid, THREADS>>>(x, kernels, bias, out, ntiles);
}